// round 1
// baseline (speedup 1.0000x reference)
#include <cuda_runtime.h>
#include <math.h>

// Problem constants
#define NX 128
#define NG 64
#define P  8192          // NX*NG
#define T_STEPS 4
#define N_ITER 50
#define KAPPA 0.8f
#define LAMDA 0.9f
#define YITA  0.1f
#define NEG_SLOPE 0.01f

// Matvec tiling: split-K over rows
#define RB 128            // row blocks
#define CB 32             // col blocks (256 cols each)
#define ROWS_PER_BLOCK (P / RB)   // 64

// Device scratch (static allocation is the sanctioned path — no cudaMalloc)
__device__ float g_h[P];
__device__ float g_part[RB * P];      // 4 MB split-K partials
__device__ float g_u[3 * P];          // rank-1 update vectors u_s = p+h
__device__ float g_v[3 * P];          // v_s = p-h
__device__ float g_dots[3];           // h . u_s for current iteration
__device__ float g_loss;

__device__ __forceinline__ float f_p(float v) {
    float c = fminf(fmaxf(v, -1.0f), 1.0f);
    return (c >= 0.0f) ? c : NEG_SLOPE * c;
}

// K1: y_part[rb][col] = sum_{j in rb-chunk} h[j] * M0[j, col]
//     plus one extra block computing dots d_s = h . u_s  (s < nterms)
__global__ void k_matvec(const float* __restrict__ M, int nterms) {
    int b = blockIdx.x;
    int tid = threadIdx.x;

    if (b == RB * CB) {
        // dot-product block (deterministic tree reduction)
        __shared__ float red[256];
        for (int s = 0; s < nterms; ++s) {
            float a = 0.0f;
            const float* u = g_u + s * P;
            for (int k = tid; k < P; k += 256) a = fmaf(g_h[k], u[k], a);
            red[tid] = a;
            __syncthreads();
            for (int o = 128; o > 0; o >>= 1) {
                if (tid < o) red[tid] += red[tid + o];
                __syncthreads();
            }
            if (tid == 0) g_dots[s] = red[0];
            __syncthreads();
        }
        return;
    }

    int cb = b & (CB - 1);
    int rb = b >> 5;  // b / CB

    __shared__ float sh[ROWS_PER_BLOCK];
    if (tid < ROWS_PER_BLOCK) sh[tid] = g_h[rb * ROWS_PER_BLOCK + tid];
    __syncthreads();

    int col = cb * 256 + tid;
    const float* Mp = M + (size_t)rb * ROWS_PER_BLOCK * P + col;

    float acc = 0.0f;
#pragma unroll 16
    for (int j = 0; j < ROWS_PER_BLOCK; ++j) {
        acc = fmaf(sh[j], Mp[(size_t)j * P], acc);
    }
    g_part[rb * P + col] = acc;
}

// K2: reduce partials, add rank-1 corrections, pointwise attractor update
__global__ void k_update(float lam_pow, float c0, float c1, float c2, int nterms) {
    int col = blockIdx.x * 64 + threadIdx.x;
    float y = 0.0f;
#pragma unroll
    for (int r = 0; r < RB; ++r) y += g_part[r * P + col];
    y *= lam_pow;
    if (nterms > 0) y = fmaf(c0 * g_dots[0], g_v[0 * P + col], y);
    if (nterms > 1) y = fmaf(c1 * g_dots[1], g_v[1 * P + col], y);
    if (nterms > 2) y = fmaf(c2 * g_dots[2], g_v[2 * P + col], y);
    float h = g_h[col];
    g_h[col] = f_p(KAPPA * h + h * y);
}

// Per-step init: h0 = f_p(tile(g_t, NX)); zero loss accumulator at t==0
__global__ void k_init(const float* __restrict__ g, int t) {
    int k = blockIdx.x * 256 + threadIdx.x;
    g_h[k] = f_p(g[t * NG + (k & (NG - 1))]);
    if (t == 0 && k == 0) g_loss = 0.0f;
}

// Per-step finalize: loss += sum |p - h|; store u_t = p+h, v_t = p-h; write out
__global__ void k_final(const float* __restrict__ x, const float* __restrict__ g,
                        int t, float* __restrict__ out) {
    __shared__ float red[256];
    int tid = threadIdx.x;
    float a = 0.0f;
    for (int k = tid; k < P; k += 256) {
        float p = x[t * NX + (k >> 6)] * g[t * NG + (k & (NG - 1))];
        float h = g_h[k];
        if (t < 3) {
            g_u[t * P + k] = p + h;
            g_v[t * P + k] = p - h;
        }
        a += fabsf(p - h);
    }
    red[tid] = a;
    __syncthreads();
    for (int o = 128; o > 0; o >>= 1) {
        if (tid < o) red[tid] += red[tid + o];
        __syncthreads();
    }
    if (tid == 0) {
        g_loss += red[0];
        *out = g_loss;
    }
}

extern "C" void kernel_launch(void* const* d_in, const int* in_sizes, int n_in,
                              void* d_out, int out_size) {
    const float* x = (const float*)d_in[0];   // [4,128]
    const float* g = (const float*)d_in[1];   // [4,64]
    const float* M = (const float*)d_in[2];   // [8192,8192]
    float* out = (float*)d_out;
    (void)in_sizes; (void)n_in; (void)out_size;

    for (int t = 0; t < T_STEPS; ++t) {
        k_init<<<P / 256, 256>>>(g, t);

        float lam_pow = 1.0f;
        for (int i = 0; i < t; ++i) lam_pow *= LAMDA;
        float c[3] = {0.0f, 0.0f, 0.0f};
        for (int s = 0; s < t; ++s) {
            float lp = 1.0f;
            for (int i = 0; i < t - 1 - s; ++i) lp *= LAMDA;
            c[s] = YITA * lp;
        }

        for (int it = 0; it < N_ITER; ++it) {
            k_matvec<<<RB * CB + 1, 256>>>(M, t);
            k_update<<<P / 64, 64>>>(lam_pow, c[0], c[1], c[2], t);
        }

        k_final<<<1, 256>>>(x, g, t, out);
    }
}

// round 2
// speedup vs baseline: 1.8851x; 1.8851x over previous
#include <cuda_runtime.h>
#include <cuda_fp16.h>
#include <math.h>

// Problem constants
#define NX 128
#define NG 64
#define P  8192          // NX*NG
#define T_STEPS 4
#define N_ITER 50
#define KAPPA 0.8f
#define LAMDA 0.9f
#define YITA  0.1f
#define NEG_SLOPE 0.01f

// Matvec tiling: split-K over rows, fp16 matrix
#define RB 64                     // row chunks
#define ROWS_PER_CHUNK (P / RB)   // 128
#define CB2 8                     // column blocks (1024 cols each: 256 thr x 4 cols)

// Device scratch (static __device__ arrays — the sanctioned path)
__device__ __half g_M16[(size_t)P * P];   // 128 MB fp16 copy of M0
__device__ float g_h[P];
__device__ float g_part[RB * P];          // 2 MB split-K partials
__device__ float g_u[3 * P];              // rank-1 vectors u_s = p+h
__device__ float g_v[3 * P];              // v_s = p-h
__device__ float g_dots[3];               // h . u_s
__device__ float g_loss;

__device__ __forceinline__ float f_p(float v) {
    float c = fminf(fmaxf(v, -1.0f), 1.0f);
    return (c >= 0.0f) ? c : NEG_SLOPE * c;
}

// Convert M0 fp32 -> fp16 (runs once per replay; ~60us)
__global__ void k_convert(const float* __restrict__ M) {
    size_t i = ((size_t)blockIdx.x * blockDim.x + threadIdx.x) * 8;
    const float4* src = (const float4*)(M + i);
    float4 a = src[0];
    float4 b = src[1];
    __half2 h0 = __floats2half2_rn(a.x, a.y);
    __half2 h1 = __floats2half2_rn(a.z, a.w);
    __half2 h2 = __floats2half2_rn(b.x, b.y);
    __half2 h3 = __floats2half2_rn(b.z, b.w);
    uint4 out;
    out.x = *(unsigned*)&h0;
    out.y = *(unsigned*)&h1;
    out.z = *(unsigned*)&h2;
    out.w = *(unsigned*)&h3;
    *(uint4*)(g_M16 + i) = out;
}

// K1: partials[rb][col] = sum_{j in chunk rb} h[j] * M16[j, col]
//     + one extra block computing dots d_s = h . u_s
__global__ void k_matvec(int nterms) {
    int b = blockIdx.x;
    int tid = threadIdx.x;

    if (b == RB * CB2) {
        __shared__ float red[256];
        for (int s = 0; s < nterms; ++s) {
            float a = 0.0f;
            const float* u = g_u + s * P;
            for (int k = tid; k < P; k += 256) a = fmaf(g_h[k], u[k], a);
            red[tid] = a;
            __syncthreads();
            for (int o = 128; o > 0; o >>= 1) {
                if (tid < o) red[tid] += red[tid + o];
                __syncthreads();
            }
            if (tid == 0) g_dots[s] = red[0];
            __syncthreads();
        }
        return;
    }

    int cb = b & (CB2 - 1);
    int rb = b >> 3;

    __shared__ float sh[ROWS_PER_CHUNK];
    if (tid < ROWS_PER_CHUNK) sh[tid] = g_h[rb * ROWS_PER_CHUNK + tid];
    __syncthreads();

    // each thread: 4 consecutive columns via one uint2 (4 halves) per row
    int idx = cb * 256 + tid;  // uint2 index within a row
    const uint2* row = (const uint2*)(g_M16 + (size_t)rb * ROWS_PER_CHUNK * P);
    row += idx;

    float4 acc = make_float4(0.f, 0.f, 0.f, 0.f);
#pragma unroll 8
    for (int j = 0; j < ROWS_PER_CHUNK; ++j) {
        uint2 m = *row;
        row += P / 4;  // next row (P halves = P/4 uint2)
        float2 fa = __half22float2(*(__half2*)&m.x);
        float2 fb = __half22float2(*(__half2*)&m.y);
        float hv = sh[j];
        acc.x = fmaf(hv, fa.x, acc.x);
        acc.y = fmaf(hv, fa.y, acc.y);
        acc.z = fmaf(hv, fb.x, acc.z);
        acc.w = fmaf(hv, fb.y, acc.w);
    }
    *(float4*)(g_part + (size_t)rb * P + (cb * 1024 + tid * 4)) = acc;
}

// K2: reduce partials, add rank-1 corrections, pointwise attractor update
__global__ void k_update(float lam_pow, float c0, float c1, float c2, int nterms) {
    int col = blockIdx.x * 256 + threadIdx.x;
    float y = 0.0f;
#pragma unroll
    for (int r = 0; r < RB; ++r) y += g_part[r * P + col];
    y *= lam_pow;
    if (nterms > 0) y = fmaf(c0 * g_dots[0], g_v[0 * P + col], y);
    if (nterms > 1) y = fmaf(c1 * g_dots[1], g_v[1 * P + col], y);
    if (nterms > 2) y = fmaf(c2 * g_dots[2], g_v[2 * P + col], y);
    float h = g_h[col];
    g_h[col] = f_p(KAPPA * h + h * y);
}

// Per-step init: h0 = f_p(tile(g_t, NX)); zero loss accumulator at t==0
__global__ void k_init(const float* __restrict__ g, int t) {
    int k = blockIdx.x * 256 + threadIdx.x;
    g_h[k] = f_p(g[t * NG + (k & (NG - 1))]);
    if (t == 0 && k == 0) g_loss = 0.0f;
}

// Per-step finalize: loss += sum |p - h|; store u_t = p+h, v_t = p-h
__global__ void k_final(const float* __restrict__ x, const float* __restrict__ g,
                        int t, float* __restrict__ out) {
    __shared__ float red[256];
    int tid = threadIdx.x;
    float a = 0.0f;
    for (int k = tid; k < P; k += 256) {
        float p = x[t * NX + (k >> 6)] * g[t * NG + (k & (NG - 1))];
        float h = g_h[k];
        if (t < 3) {
            g_u[t * P + k] = p + h;
            g_v[t * P + k] = p - h;
        }
        a += fabsf(p - h);
    }
    red[tid] = a;
    __syncthreads();
    for (int o = 128; o > 0; o >>= 1) {
        if (tid < o) red[tid] += red[tid + o];
        __syncthreads();
    }
    if (tid == 0) {
        g_loss += red[0];
        *out = g_loss;
    }
}

extern "C" void kernel_launch(void* const* d_in, const int* in_sizes, int n_in,
                              void* d_out, int out_size) {
    const float* x = (const float*)d_in[0];   // [4,128]
    const float* g = (const float*)d_in[1];   // [4,64]
    const float* M = (const float*)d_in[2];   // [8192,8192]
    float* out = (float*)d_out;
    (void)in_sizes; (void)n_in; (void)out_size;

    // fp16 copy of M0 (must run each replay: deterministic, graph-capturable)
    k_convert<<<(P * (size_t)P / 8 + 255) / 256, 256>>>(M);

    for (int t = 0; t < T_STEPS; ++t) {
        k_init<<<P / 256, 256>>>(g, t);

        float lam_pow = 1.0f;
        for (int i = 0; i < t; ++i) lam_pow *= LAMDA;
        float c[3] = {0.0f, 0.0f, 0.0f};
        for (int s = 0; s < t; ++s) {
            float lp = 1.0f;
            for (int i = 0; i < t - 1 - s; ++i) lp *= LAMDA;
            c[s] = YITA * lp;
        }

        for (int it = 0; it < N_ITER; ++it) {
            k_matvec<<<RB * CB2 + 1, 256>>>(t);
            k_update<<<P / 256, 256>>>(lam_pow, c[0], c[1], c[2], t);
        }

        k_final<<<1, 256>>>(x, g, t, out);
    }
}

// round 3
// speedup vs baseline: 1.9312x; 1.0245x over previous
#include <cuda_runtime.h>
#include <cuda_fp16.h>
#include <math.h>

// Problem constants
#define NX 128
#define NG 64
#define P  8192          // NX*NG
#define T_STEPS 4
#define N_ITER 50
#define KAPPA 0.8f
#define LAMDA 0.9f
#define YITA  0.1f
#define NEG_SLOPE 0.01f

// Matvec tiling: split-K over rows, fp16 matrix
#define RB 64                     // row chunks
#define ROWS_PER_CHUNK (P / RB)   // 128
#define CB2 8                     // column blocks (1024 cols each: 256 thr x 4 cols)

// Device scratch (static __device__ arrays — the sanctioned path)
__device__ __half g_M16[(size_t)P * P];   // 128 MB fp16 copy of M0
__device__ float g_h[P];
__device__ float g_part[RB * P];          // 2 MB split-K partials
__device__ float g_u[3 * P];              // rank-1 vectors u_s = p+h
__device__ float g_v[3 * P];              // v_s = p-h
__device__ float g_dots[3];               // h . u_s
__device__ float g_loss;

__device__ __forceinline__ float f_p(float v) {
    float c = fminf(fmaxf(v, -1.0f), 1.0f);
    return (c >= 0.0f) ? c : NEG_SLOPE * c;
}

// Convert M0 fp32 -> fp16 (runs once per replay)
__global__ void k_convert(const float* __restrict__ M) {
    size_t i = ((size_t)blockIdx.x * blockDim.x + threadIdx.x) * 8;
    const float4* src = (const float4*)(M + i);
    float4 a = src[0];
    float4 b = src[1];
    __half2 h0 = __floats2half2_rn(a.x, a.y);
    __half2 h1 = __floats2half2_rn(a.z, a.w);
    __half2 h2 = __floats2half2_rn(b.x, b.y);
    __half2 h3 = __floats2half2_rn(b.z, b.w);
    uint4 out;
    out.x = *(unsigned*)&h0;
    out.y = *(unsigned*)&h1;
    out.z = *(unsigned*)&h2;
    out.w = *(unsigned*)&h3;
    *(uint4*)(g_M16 + i) = out;
}

// K1: partials[rb][col] = sum_{j in chunk rb} h[j] * M16[j, col]
//     + (optional) one extra block computing dots d_s = h . u_s
__global__ void k_matvec(int nterms) {
    int b = blockIdx.x;
    int tid = threadIdx.x;

    if (b == RB * CB2) {
        __shared__ float red[256];
        for (int s = 0; s < nterms; ++s) {
            float a = 0.0f;
            const float* __restrict__ u = g_u + s * P;
            const float* __restrict__ hh = g_h;
            for (int k = tid; k < P; k += 256) a = fmaf(hh[k], u[k], a);
            red[tid] = a;
            __syncthreads();
            for (int o = 128; o > 0; o >>= 1) {
                if (tid < o) red[tid] += red[tid + o];
                __syncthreads();
            }
            if (tid == 0) g_dots[s] = red[0];
            __syncthreads();
        }
        return;
    }

    int cb = b & (CB2 - 1);
    int rb = b >> 3;

    __shared__ float sh[ROWS_PER_CHUNK];
    if (tid < ROWS_PER_CHUNK) sh[tid] = g_h[rb * ROWS_PER_CHUNK + tid];
    __syncthreads();

    // each thread: 4 consecutive columns via one uint2 (4 halves) per row
    int idx = cb * 256 + tid;  // uint2 index within a row
    const uint2* __restrict__ row =
        (const uint2*)(g_M16 + (size_t)rb * ROWS_PER_CHUNK * P) + idx;

    float4 acc = make_float4(0.f, 0.f, 0.f, 0.f);
#pragma unroll 8
    for (int j = 0; j < ROWS_PER_CHUNK; ++j) {
        uint2 m = __ldg(row);
        row += P / 4;  // next row (P halves = P/4 uint2)
        float2 fa = __half22float2(*(__half2*)&m.x);
        float2 fb = __half22float2(*(__half2*)&m.y);
        float hv = sh[j];
        acc.x = fmaf(hv, fa.x, acc.x);
        acc.y = fmaf(hv, fa.y, acc.y);
        acc.z = fmaf(hv, fb.x, acc.z);
        acc.w = fmaf(hv, fb.y, acc.w);
    }
    *(float4*)(g_part + (size_t)rb * P + (cb * 1024 + tid * 4)) = acc;
}

// K2: reduce partials (lane-parallel), rank-1 corrections, pointwise update.
// Grid: 256 blocks x 256 threads. Block handles 32 columns.
// Thread layout: lane c = tid & 31 -> column; lane l = tid >> 5 (0..7) -> sums
// partials l*8 .. l*8+7. Consecutive threads hit consecutive columns (coalesced).
__global__ void k_update(float lam_pow, float c0, float c1, float c2, int nterms) {
    __shared__ float red[8][32];
    int tid = threadIdx.x;
    int c = tid & 31;
    int l = tid >> 5;
    int col = blockIdx.x * 32 + c;

    float y = 0.0f;
    const float* __restrict__ part = g_part + (size_t)(l * 8) * P + col;
#pragma unroll
    for (int k = 0; k < 8; ++k) y += part[(size_t)k * P];
    red[l][c] = y;
    __syncthreads();

    if (l == 0) {
        float s = red[0][c];
#pragma unroll
        for (int k = 1; k < 8; ++k) s += red[k][c];
        s *= lam_pow;
        if (nterms > 0) s = fmaf(c0 * g_dots[0], g_v[0 * P + col], s);
        if (nterms > 1) s = fmaf(c1 * g_dots[1], g_v[1 * P + col], s);
        if (nterms > 2) s = fmaf(c2 * g_dots[2], g_v[2 * P + col], s);
        float h = g_h[col];
        g_h[col] = f_p(KAPPA * h + h * s);
    }
}

// Per-step init: h0 = f_p(tile(g_t, NX)); zero loss accumulator at t==0
__global__ void k_init(const float* __restrict__ g, int t) {
    int k = blockIdx.x * 256 + threadIdx.x;
    g_h[k] = f_p(g[t * NG + (k & (NG - 1))]);
    if (t == 0 && k == 0) g_loss = 0.0f;
}

// Per-step finalize: loss += sum |p - h|; store u_t = p+h, v_t = p-h
__global__ void k_final(const float* __restrict__ x, const float* __restrict__ g,
                        int t, float* __restrict__ out) {
    __shared__ float red[256];
    int tid = threadIdx.x;
    float a = 0.0f;
    for (int k = tid; k < P; k += 256) {
        float p = x[t * NX + (k >> 6)] * g[t * NG + (k & (NG - 1))];
        float h = g_h[k];
        if (t < 3) {
            g_u[t * P + k] = p + h;
            g_v[t * P + k] = p - h;
        }
        a += fabsf(p - h);
    }
    red[tid] = a;
    __syncthreads();
    for (int o = 128; o > 0; o >>= 1) {
        if (tid < o) red[tid] += red[tid + o];
        __syncthreads();
    }
    if (tid == 0) {
        g_loss += red[0];
        *out = g_loss;
    }
}

extern "C" void kernel_launch(void* const* d_in, const int* in_sizes, int n_in,
                              void* d_out, int out_size) {
    const float* x = (const float*)d_in[0];   // [4,128]
    const float* g = (const float*)d_in[1];   // [4,64]
    const float* M = (const float*)d_in[2];   // [8192,8192]
    float* out = (float*)d_out;
    (void)in_sizes; (void)n_in; (void)out_size;

    // fp16 copy of M0 (runs each replay: deterministic, graph-capturable)
    k_convert<<<(P * (size_t)P / 8 + 255) / 256, 256>>>(M);

    for (int t = 0; t < T_STEPS; ++t) {
        k_init<<<P / 256, 256>>>(g, t);

        float lam_pow = 1.0f;
        for (int i = 0; i < t; ++i) lam_pow *= LAMDA;
        float c[3] = {0.0f, 0.0f, 0.0f};
        for (int s = 0; s < t; ++s) {
            float lp = 1.0f;
            for (int i = 0; i < t - 1 - s; ++i) lp *= LAMDA;
            c[s] = YITA * lp;
        }

        int mv_grid = RB * CB2 + (t > 0 ? 1 : 0);
        for (int it = 0; it < N_ITER; ++it) {
            k_matvec<<<mv_grid, 256>>>(t);
            k_update<<<P / 32, 256>>>(lam_pow, c[0], c[1], c[2], t);
        }

        k_final<<<1, 256>>>(x, g, t, out);
    }
}